// round 5
// baseline (speedup 1.0000x reference)
#include <cuda_runtime.h>
#include <math.h>

#define SEQ  4096
#define EMB  512
#define HH   512
#define G4   2048          // 4*H per direction
#define NT   4096          // gate columns, both directions
#define TAGS 24
#define START_TAG 22
#define STOP_TAG  23
#define NEGV (-10000.0f)

// ---------------- persistent device scratch (no allocations allowed) ----------
__device__ float d_xg[SEQ][NT];          // 64 MB: input projections + biases
__device__ float d_hall[2][SEQ][HH];     // 16 MB: hf / hb history
__device__ float d_feats[SEQ][TAGS];     // tag features
__device__ int   d_cnt[2];               // per-direction step barrier counters

// ---------------- init: reset barrier counters every launch -------------------
__global__ void init_kernel() {
    if (threadIdx.x < 2) d_cnt[threadIdx.x] = 0;
}

// ---------------- kernel 1: gather + input projection GEMM --------------------
// C[t][n] = emb[sentence[t]] . w_ih[n] + (b_ih[n]+b_hh[n]), n<2048 fwd, else bwd
__global__ void __launch_bounds__(256) gemm_xg_kernel(
    const int* __restrict__ sent, const float* __restrict__ emb,
    const float* __restrict__ w_ih_f, const float* __restrict__ w_ih_b,
    const float* __restrict__ b_ih_f, const float* __restrict__ b_hh_f,
    const float* __restrict__ b_ih_b, const float* __restrict__ b_hh_b)
{
    __shared__ float As[16][132];
    __shared__ float Bs[16][132];
    __shared__ int ssent[128];
    const int tid = threadIdx.x;
    const int bm = blockIdx.y, bn = blockIdx.x;
    if (tid < 128) ssent[tid] = sent[bm * 128 + tid];
    __syncthreads();
    const int tx = tid & 15, ty = tid >> 4;

    float acc[8][8];
#pragma unroll
    for (int j = 0; j < 8; j++) {
        int n = bn * 128 + tx * 8 + j;
        float b = (n < G4) ? (b_ih_f[n] + b_hh_f[n]) : (b_ih_b[n - G4] + b_hh_b[n - G4]);
#pragma unroll
        for (int i = 0; i < 8; i++) acc[i][j] = b;
    }

    for (int kt = 0; kt < EMB; kt += 16) {
#pragma unroll
        for (int r = 0; r < 2; r++) {
            int e = tid + r * 256;
            int m = e >> 2, kv = (e & 3) << 2;
            float4 v = *(const float4*)(emb + (size_t)ssent[m] * EMB + kt + kv);
            As[kv + 0][m] = v.x; As[kv + 1][m] = v.y; As[kv + 2][m] = v.z; As[kv + 3][m] = v.w;
        }
#pragma unroll
        for (int r = 0; r < 2; r++) {
            int e = tid + r * 256;
            int n = e >> 2, kv = (e & 3) << 2;
            int ng = bn * 128 + n;
            const float* w = (ng < G4) ? (w_ih_f + (size_t)ng * EMB)
                                       : (w_ih_b + (size_t)(ng - G4) * EMB);
            float4 v = *(const float4*)(w + kt + kv);
            Bs[kv + 0][n] = v.x; Bs[kv + 1][n] = v.y; Bs[kv + 2][n] = v.z; Bs[kv + 3][n] = v.w;
        }
        __syncthreads();
#pragma unroll
        for (int kk = 0; kk < 16; kk++) {
            float4 a0 = *(const float4*)&As[kk][ty * 8];
            float4 a1 = *(const float4*)&As[kk][ty * 8 + 4];
            float4 b0 = *(const float4*)&Bs[kk][tx * 8];
            float4 b1 = *(const float4*)&Bs[kk][tx * 8 + 4];
            float a[8] = {a0.x, a0.y, a0.z, a0.w, a1.x, a1.y, a1.z, a1.w};
            float b[8] = {b0.x, b0.y, b0.z, b0.w, b1.x, b1.y, b1.z, b1.w};
#pragma unroll
            for (int i = 0; i < 8; i++)
#pragma unroll
                for (int j = 0; j < 8; j++)
                    acc[i][j] = fmaf(a[i], b[j], acc[i][j]);
        }
        __syncthreads();
    }
#pragma unroll
    for (int i = 0; i < 8; i++) {
        float* dst = &d_xg[bm * 128 + ty * 8 + i][bn * 128 + tx * 8];
        *(float4*)dst       = make_float4(acc[i][0], acc[i][1], acc[i][2], acc[i][3]);
        *(float4*)(dst + 4) = make_float4(acc[i][4], acc[i][5], acc[i][6], acc[i][7]);
    }
}

// ---------------- kernel 2: persistent BiLSTM recurrence ----------------------
// 128 CTAs x 128 threads. CTA c: dir = c/64, owns 8 h-indices (32 gate rows).
// w_hh slice register-resident (128 f32/thread). Per-step device barrier via
// counter in L2; h broadcast through d_hall.
__global__ void __launch_bounds__(128, 1) lstm_rec_kernel(
    const float* __restrict__ w_hh_f, const float* __restrict__ w_hh_b,
    const float* __restrict__ h0, const float* __restrict__ c0)
{
    const int cta = blockIdx.x;
    const int dir = cta >> 6;           // 0 fwd, 1 bwd
    const int cc  = cta & 63;
    const int tid = threadIdx.x;
    const int kq  = tid >> 5;           // k-quarter (warp id): 128 k-values
    const int lr  = tid & 31;           // local gate row 0..31
    const int hbase  = cc << 3;         // 8 h per CTA
    const int gate   = lr >> 3;
    const int within = lr & 7;
    const int grow   = gate * HH + hbase + within;   // row in w_hh [2048,512]

    const float* w_hh = dir ? w_hh_b : w_hh_f;
    float w[128];
    {
        const float4* wp = (const float4*)(w_hh + (size_t)grow * HH + kq * 128);
#pragma unroll
        for (int i = 0; i < 32; i++) {
            float4 v = wp[i];
            w[4 * i + 0] = v.x; w[4 * i + 1] = v.y; w[4 * i + 2] = v.z; w[4 * i + 3] = v.w;
        }
    }

    __shared__ float4 h_sh[128];        // current h (512 f32)
    __shared__ float  part_sh[4][32];

    h_sh[tid] = ((const float4*)(h0 + dir * HH))[tid];

    float c = 0.f, xv0 = 0.f, xv1 = 0.f, xv2 = 0.f, xv3 = 0.f;
    if (tid < 8) {
        c = c0[dir * HH + hbase + tid];
        int t0 = dir ? (SEQ - 1) : 0;
        const float* xr = &d_xg[t0][dir * G4];
        xv0 = xr[0 * HH + hbase + tid];
        xv1 = xr[1 * HH + hbase + tid];
        xv2 = xr[2 * HH + hbase + tid];
        xv3 = xr[3 * HH + hbase + tid];
    }
    __syncthreads();

    volatile int* vcnt = (volatile int*)&d_cnt[dir];

    for (int s = 0; s < SEQ; s++) {
        const int t = dir ? (SEQ - 1 - s) : s;

        // partial GEMV: 128 FMA per thread, h broadcast within warp
        float a0 = 0.f, a1 = 0.f, a2 = 0.f, a3 = 0.f;
#pragma unroll
        for (int i = 0; i < 32; i++) {
            float4 hv = h_sh[kq * 32 + i];
            a0 = fmaf(w[4 * i + 0], hv.x, a0);
            a1 = fmaf(w[4 * i + 1], hv.y, a1);
            a2 = fmaf(w[4 * i + 2], hv.z, a2);
            a3 = fmaf(w[4 * i + 3], hv.w, a3);
        }
        part_sh[kq][lr] = (a0 + a1) + (a2 + a3);
        __syncthreads();                                    // S1

        if (tid < 8) {
            float gi = part_sh[0][tid]        + part_sh[1][tid]        + part_sh[2][tid]        + part_sh[3][tid]        + xv0;
            float gf = part_sh[0][8  + tid]   + part_sh[1][8  + tid]   + part_sh[2][8  + tid]   + part_sh[3][8  + tid]   + xv1;
            float gg = part_sh[0][16 + tid]   + part_sh[1][16 + tid]   + part_sh[2][16 + tid]   + part_sh[3][16 + tid]   + xv2;
            float go = part_sh[0][24 + tid]   + part_sh[1][24 + tid]   + part_sh[2][24 + tid]   + part_sh[3][24 + tid]   + xv3;
            float ig = 1.f / (1.f + expf(-gi));
            float fg = 1.f / (1.f + expf(-gf));
            float gt = tanhf(gg);
            float og = 1.f / (1.f + expf(-go));
            c = fmaf(fg, c, ig * gt);
            float h = og * tanhf(c);
            d_hall[dir][t][hbase + tid] = h;
            if (s + 1 < SEQ) {                              // prefetch next xg
                int tn = dir ? (t - 1) : (t + 1);
                const float* xr = &d_xg[tn][dir * G4];
                xv0 = xr[0 * HH + hbase + tid];
                xv1 = xr[1 * HH + hbase + tid];
                xv2 = xr[2 * HH + hbase + tid];
                xv3 = xr[3 * HH + hbase + tid];
            }
            __threadfence();                                // release h store
        }
        __syncthreads();                                    // S2

        if (tid == 0) {
            atomicAdd(&d_cnt[dir], 1);
            const int target = 64 * (s + 1);
            while (*vcnt < target) { }
            __threadfence();                                // acquire
        }
        __syncthreads();                                    // S3

        float4 hv = ((const float4*)&d_hall[dir][t][0])[tid];
        h_sh[tid] = hv;
        __syncthreads();                                    // S4
    }
}

// ---------------- kernel 3: tag features feats[t] = [hf,hb] @ w_tag^T + b ----
__global__ void __launch_bounds__(256) feats_kernel(
    const float* __restrict__ w_tag, const float* __restrict__ b_tag)
{
    __shared__ float hsh[4][1024];
    const int t0  = blockIdx.x * 4;
    const int tid = threadIdx.x;
    for (int i = tid; i < 1024; i += 256) {       // 1024 float4 = 4 rows x 1024 f32
        int tt = i >> 8;
        int kk = i & 255;
        float4 v = (kk < 128) ? ((const float4*)&d_hall[0][t0 + tt][0])[kk]
                              : ((const float4*)&d_hall[1][t0 + tt][0])[kk - 128];
        ((float4*)&hsh[tt][0])[kk] = v;
    }
    __syncthreads();
    const int warp = tid >> 5, lane = tid & 31;
#pragma unroll
    for (int jj = 0; jj < 3; jj++) {
        int j = warp * 3 + jj;
        float4 wv[8];
#pragma unroll
        for (int q = 0; q < 8; q++)
            wv[q] = ((const float4*)(w_tag + j * 1024))[lane + q * 32];
#pragma unroll
        for (int tt = 0; tt < 4; tt++) {
            float s = 0.f;
#pragma unroll
            for (int q = 0; q < 8; q++) {
                float4 hv = ((const float4*)&hsh[tt][0])[lane + q * 32];
                s = fmaf(wv[q].x, hv.x, s);
                s = fmaf(wv[q].y, hv.y, s);
                s = fmaf(wv[q].z, hv.z, s);
                s = fmaf(wv[q].w, hv.w, s);
            }
#pragma unroll
            for (int o = 16; o; o >>= 1) s += __shfl_down_sync(0xffffffffu, s, o);
            if (lane == 0) d_feats[t0 + tt][j] = s + b_tag[j];
        }
    }
}

// ---------------- kernel 4: Viterbi forward + backtrace (1 warp) --------------
// backpointers live in 96KB shared (uint8) so backtrace is LDS-latency.
__global__ void viterbi_kernel(const float* __restrict__ transitions,
                               float* __restrict__ out)
{
    extern __shared__ unsigned char vsmem[];
    unsigned char (*bp)[TAGS] = (unsigned char(*)[TAGS])vsmem;
    float* fv = (float*)(vsmem + SEQ * TAGS);
    __shared__ float term[TAGS];

    const int j = threadIdx.x;            // 32 threads, 24 active
    float trow[TAGS];
    if (j < TAGS) {
#pragma unroll
        for (int p = 0; p < TAGS; p++) trow[p] = transitions[j * TAGS + p];
        fv[j] = (j == START_TAG) ? 0.f : NEGV;
    }
    __syncwarp();

    float featn = (j < TAGS) ? d_feats[0][j] : 0.f;
    for (int t = 0; t < SEQ; t++) {
        float feat = featn;
        if (j < TAGS && t + 1 < SEQ) featn = d_feats[t + 1][j];
        float best = 0.f; int arg = 0;
        if (j < TAGS) {
            best = trow[0] + fv[0]; arg = 0;
#pragma unroll
            for (int p = 1; p < TAGS; p++) {
                float v = trow[p] + fv[p];
                if (v > best) { best = v; arg = p; }
            }
            bp[t][j] = (unsigned char)arg;
        }
        __syncwarp();
        if (j < TAGS) fv[j] = best + feat;
        __syncwarp();
    }

    if (j < TAGS) term[j] = fv[j] + transitions[STOP_TAG * TAGS + j];
    __syncwarp();
    if (j == 0) {
        float bs = term[0]; int bt = 0;
#pragma unroll
        for (int p = 1; p < TAGS; p++) if (term[p] > bs) { bs = term[p]; bt = p; }
        out[0] = bs;                       // path_score
        int cur = bt;
        out[SEQ] = (float)bt;              // path[4095]
        for (int t = SEQ - 1; t >= 1; --t) {
            cur = bp[t][cur];
            out[t] = (float)cur;           // path[t-1] -> out[1+(t-1)]
        }
    }
}

// ---------------- launcher ----------------------------------------------------
extern "C" void kernel_launch(void* const* d_in, const int* in_sizes, int n_in,
                              void* d_out, int out_size)
{
    const int*   sentence = (const int*)d_in[0];
    const float* emb      = (const float*)d_in[1];
    const float* w_ih_f   = (const float*)d_in[2];
    const float* w_hh_f   = (const float*)d_in[3];
    const float* b_ih_f   = (const float*)d_in[4];
    const float* b_hh_f   = (const float*)d_in[5];
    const float* w_ih_b   = (const float*)d_in[6];
    const float* w_hh_b   = (const float*)d_in[7];
    const float* b_ih_b   = (const float*)d_in[8];
    const float* b_hh_b   = (const float*)d_in[9];
    const float* w_tag    = (const float*)d_in[10];
    const float* b_tag    = (const float*)d_in[11];
    const float* trans    = (const float*)d_in[12];
    const float* h0       = (const float*)d_in[13];
    const float* c0       = (const float*)d_in[14];
    float* out = (float*)d_out;

    const int vit_smem = SEQ * TAGS + 128;   // 98432 bytes
    cudaFuncSetAttribute(viterbi_kernel,
                         cudaFuncAttributeMaxDynamicSharedMemorySize, vit_smem);

    init_kernel<<<1, 32>>>();

    dim3 ggrid(32, 32);
    gemm_xg_kernel<<<ggrid, 256>>>(sentence, emb, w_ih_f, w_ih_b,
                                   b_ih_f, b_hh_f, b_ih_b, b_hh_b);

    lstm_rec_kernel<<<128, 128>>>(w_hh_f, w_hh_b, h0, c0);

    feats_kernel<<<1024, 256>>>(w_tag, b_tag);

    viterbi_kernel<<<1, 32, vit_smem>>>(trans, out);
}

// round 6
// speedup vs baseline: 1.0165x; 1.0165x over previous
#include <cuda_runtime.h>
#include <math.h>

#define SEQ  4096
#define EMB  512
#define HH   512
#define G4   2048          // 4*H per direction
#define NT   4096          // gate columns, both directions
#define TAGS 24
#define START_TAG 22
#define STOP_TAG  23
#define NEGV (-10000.0f)

// ---------------- persistent device scratch (no allocations allowed) ----------
__device__ float d_xg[SEQ][NT];          // 64 MB: input projections + biases
__device__ float d_hall[2][SEQ][HH];     // 16 MB: hf / hb history
__device__ float d_feats[SEQ][TAGS];     // tag features
__device__ int   d_cnt[2];               // per-direction step barrier counters

// ---------------- init: reset barrier counters every launch -------------------
__global__ void init_kernel() {
    if (threadIdx.x < 2) d_cnt[threadIdx.x] = 0;
}

// ---------------- kernel 1: gather + input projection GEMM --------------------
// C[t][n] = emb[sentence[t]] . w_ih[n] + (b_ih[n]+b_hh[n]), n<2048 fwd, else bwd
__global__ void __launch_bounds__(256) gemm_xg_kernel(
    const int* __restrict__ sent, const float* __restrict__ emb,
    const float* __restrict__ w_ih_f, const float* __restrict__ w_ih_b,
    const float* __restrict__ b_ih_f, const float* __restrict__ b_hh_f,
    const float* __restrict__ b_ih_b, const float* __restrict__ b_hh_b)
{
    __shared__ float As[16][132];
    __shared__ float Bs[16][132];
    __shared__ int ssent[128];
    const int tid = threadIdx.x;
    const int bm = blockIdx.y, bn = blockIdx.x;
    if (tid < 128) ssent[tid] = sent[bm * 128 + tid];
    __syncthreads();
    const int tx = tid & 15, ty = tid >> 4;

    float acc[8][8];
#pragma unroll
    for (int j = 0; j < 8; j++) {
        int n = bn * 128 + tx * 8 + j;
        float b = (n < G4) ? (b_ih_f[n] + b_hh_f[n]) : (b_ih_b[n - G4] + b_hh_b[n - G4]);
#pragma unroll
        for (int i = 0; i < 8; i++) acc[i][j] = b;
    }

    for (int kt = 0; kt < EMB; kt += 16) {
#pragma unroll
        for (int r = 0; r < 2; r++) {
            int e = tid + r * 256;
            int m = e >> 2, kv = (e & 3) << 2;
            float4 v = *(const float4*)(emb + (size_t)ssent[m] * EMB + kt + kv);
            As[kv + 0][m] = v.x; As[kv + 1][m] = v.y; As[kv + 2][m] = v.z; As[kv + 3][m] = v.w;
        }
#pragma unroll
        for (int r = 0; r < 2; r++) {
            int e = tid + r * 256;
            int n = e >> 2, kv = (e & 3) << 2;
            int ng = bn * 128 + n;
            const float* w = (ng < G4) ? (w_ih_f + (size_t)ng * EMB)
                                       : (w_ih_b + (size_t)(ng - G4) * EMB);
            float4 v = *(const float4*)(w + kt + kv);
            Bs[kv + 0][n] = v.x; Bs[kv + 1][n] = v.y; Bs[kv + 2][n] = v.z; Bs[kv + 3][n] = v.w;
        }
        __syncthreads();
#pragma unroll
        for (int kk = 0; kk < 16; kk++) {
            float4 a0 = *(const float4*)&As[kk][ty * 8];
            float4 a1 = *(const float4*)&As[kk][ty * 8 + 4];
            float4 b0 = *(const float4*)&Bs[kk][tx * 8];
            float4 b1 = *(const float4*)&Bs[kk][tx * 8 + 4];
            float a[8] = {a0.x, a0.y, a0.z, a0.w, a1.x, a1.y, a1.z, a1.w};
            float b[8] = {b0.x, b0.y, b0.z, b0.w, b1.x, b1.y, b1.z, b1.w};
#pragma unroll
            for (int i = 0; i < 8; i++)
#pragma unroll
                for (int j = 0; j < 8; j++)
                    acc[i][j] = fmaf(a[i], b[j], acc[i][j]);
        }
        __syncthreads();
    }
#pragma unroll
    for (int i = 0; i < 8; i++) {
        float* dst = &d_xg[bm * 128 + ty * 8 + i][bn * 128 + tx * 8];
        *(float4*)dst       = make_float4(acc[i][0], acc[i][1], acc[i][2], acc[i][3]);
        *(float4*)(dst + 4) = make_float4(acc[i][4], acc[i][5], acc[i][6], acc[i][7]);
    }
}

// ---------------- kernel 2: persistent BiLSTM recurrence ----------------------
// 128 CTAs x 128 threads. CTA c: dir = c/64, owns 8 h-indices (32 gate rows).
// w_hh slice register-resident (128 f32/thread). Per-step device barrier via
// counter in L2; h broadcast through d_hall.
__global__ void __launch_bounds__(128, 1) lstm_rec_kernel(
    const float* __restrict__ w_hh_f, const float* __restrict__ w_hh_b,
    const float* __restrict__ h0, const float* __restrict__ c0)
{
    const int cta = blockIdx.x;
    const int dir = cta >> 6;           // 0 fwd, 1 bwd
    const int cc  = cta & 63;
    const int tid = threadIdx.x;
    const int kq  = tid >> 5;           // k-quarter (warp id): 128 k-values
    const int lr  = tid & 31;           // local gate row 0..31
    const int hbase  = cc << 3;         // 8 h per CTA
    const int gate   = lr >> 3;
    const int within = lr & 7;
    const int grow   = gate * HH + hbase + within;   // row in w_hh [2048,512]

    const float* w_hh = dir ? w_hh_b : w_hh_f;
    float w[128];
    {
        const float4* wp = (const float4*)(w_hh + (size_t)grow * HH + kq * 128);
#pragma unroll
        for (int i = 0; i < 32; i++) {
            float4 v = wp[i];
            w[4 * i + 0] = v.x; w[4 * i + 1] = v.y; w[4 * i + 2] = v.z; w[4 * i + 3] = v.w;
        }
    }

    __shared__ float4 h_sh[128];        // current h (512 f32)
    __shared__ float  part_sh[4][32];

    h_sh[tid] = ((const float4*)(h0 + dir * HH))[tid];

    float c = 0.f, xv0 = 0.f, xv1 = 0.f, xv2 = 0.f, xv3 = 0.f;
    if (tid < 8) {
        c = c0[dir * HH + hbase + tid];
        int t0 = dir ? (SEQ - 1) : 0;
        const float* xr = &d_xg[t0][dir * G4];
        xv0 = xr[0 * HH + hbase + tid];
        xv1 = xr[1 * HH + hbase + tid];
        xv2 = xr[2 * HH + hbase + tid];
        xv3 = xr[3 * HH + hbase + tid];
    }
    __syncthreads();

    volatile int* vcnt = (volatile int*)&d_cnt[dir];

    for (int s = 0; s < SEQ; s++) {
        const int t = dir ? (SEQ - 1 - s) : s;

        // partial GEMV: 128 FMA per thread, h broadcast within warp
        float a0 = 0.f, a1 = 0.f, a2 = 0.f, a3 = 0.f;
#pragma unroll
        for (int i = 0; i < 32; i++) {
            float4 hv = h_sh[kq * 32 + i];
            a0 = fmaf(w[4 * i + 0], hv.x, a0);
            a1 = fmaf(w[4 * i + 1], hv.y, a1);
            a2 = fmaf(w[4 * i + 2], hv.z, a2);
            a3 = fmaf(w[4 * i + 3], hv.w, a3);
        }
        part_sh[kq][lr] = (a0 + a1) + (a2 + a3);
        __syncthreads();                                    // S1

        if (tid < 8) {
            float gi = part_sh[0][tid]        + part_sh[1][tid]        + part_sh[2][tid]        + part_sh[3][tid]        + xv0;
            float gf = part_sh[0][8  + tid]   + part_sh[1][8  + tid]   + part_sh[2][8  + tid]   + part_sh[3][8  + tid]   + xv1;
            float gg = part_sh[0][16 + tid]   + part_sh[1][16 + tid]   + part_sh[2][16 + tid]   + part_sh[3][16 + tid]   + xv2;
            float go = part_sh[0][24 + tid]   + part_sh[1][24 + tid]   + part_sh[2][24 + tid]   + part_sh[3][24 + tid]   + xv3;
            float ig = 1.f / (1.f + expf(-gi));
            float fg = 1.f / (1.f + expf(-gf));
            float gt = tanhf(gg);
            float og = 1.f / (1.f + expf(-go));
            c = fmaf(fg, c, ig * gt);
            float h = og * tanhf(c);
            d_hall[dir][t][hbase + tid] = h;
            if (s + 1 < SEQ) {                              // prefetch next xg
                int tn = dir ? (t - 1) : (t + 1);
                const float* xr = &d_xg[tn][dir * G4];
                xv0 = xr[0 * HH + hbase + tid];
                xv1 = xr[1 * HH + hbase + tid];
                xv2 = xr[2 * HH + hbase + tid];
                xv3 = xr[3 * HH + hbase + tid];
            }
            __threadfence();                                // release h store
        }
        __syncthreads();                                    // S2

        if (tid == 0) {
            atomicAdd(&d_cnt[dir], 1);
            const int target = 64 * (s + 1);
            while (*vcnt < target) { }
            __threadfence();                                // acquire
        }
        __syncthreads();                                    // S3

        float4 hv = ((const float4*)&d_hall[dir][t][0])[tid];
        h_sh[tid] = hv;
        __syncthreads();                                    // S4
    }
}

// ---------------- kernel 3: tag features feats[t] = [hf,hb] @ w_tag^T + b ----
__global__ void __launch_bounds__(256) feats_kernel(
    const float* __restrict__ w_tag, const float* __restrict__ b_tag)
{
    __shared__ float hsh[4][1024];
    const int t0  = blockIdx.x * 4;
    const int tid = threadIdx.x;
    for (int i = tid; i < 1024; i += 256) {       // 1024 float4 = 4 rows x 1024 f32
        int tt = i >> 8;
        int kk = i & 255;
        float4 v = (kk < 128) ? ((const float4*)&d_hall[0][t0 + tt][0])[kk]
                              : ((const float4*)&d_hall[1][t0 + tt][0])[kk - 128];
        ((float4*)&hsh[tt][0])[kk] = v;
    }
    __syncthreads();
    const int warp = tid >> 5, lane = tid & 31;
#pragma unroll
    for (int jj = 0; jj < 3; jj++) {
        int j = warp * 3 + jj;
        float4 wv[8];
#pragma unroll
        for (int q = 0; q < 8; q++)
            wv[q] = ((const float4*)(w_tag + j * 1024))[lane + q * 32];
#pragma unroll
        for (int tt = 0; tt < 4; tt++) {
            float s = 0.f;
#pragma unroll
            for (int q = 0; q < 8; q++) {
                float4 hv = ((const float4*)&hsh[tt][0])[lane + q * 32];
                s = fmaf(wv[q].x, hv.x, s);
                s = fmaf(wv[q].y, hv.y, s);
                s = fmaf(wv[q].z, hv.z, s);
                s = fmaf(wv[q].w, hv.w, s);
            }
#pragma unroll
            for (int o = 16; o; o >>= 1) s += __shfl_down_sync(0xffffffffu, s, o);
            if (lane == 0) d_feats[t0 + tt][j] = s + b_tag[j];
        }
    }
}

// ---------------- kernel 4: Viterbi forward + backtrace (1 warp) --------------
// backpointers live in 96KB shared (uint8) so backtrace is LDS-latency.
__global__ void viterbi_kernel(const float* __restrict__ transitions,
                               float* __restrict__ out)
{
    extern __shared__ unsigned char vsmem[];
    unsigned char (*bp)[TAGS] = (unsigned char(*)[TAGS])vsmem;
    float* fv = (float*)(vsmem + SEQ * TAGS);
    __shared__ float term[TAGS];

    const int j = threadIdx.x;            // 32 threads, 24 active
    float trow[TAGS];
    if (j < TAGS) {
#pragma unroll
        for (int p = 0; p < TAGS; p++) trow[p] = transitions[j * TAGS + p];
        fv[j] = (j == START_TAG) ? 0.f : NEGV;
    }
    __syncwarp();

    float featn = (j < TAGS) ? d_feats[0][j] : 0.f;
    for (int t = 0; t < SEQ; t++) {
        float feat = featn;
        if (j < TAGS && t + 1 < SEQ) featn = d_feats[t + 1][j];
        float best = 0.f; int arg = 0;
        if (j < TAGS) {
            best = trow[0] + fv[0]; arg = 0;
#pragma unroll
            for (int p = 1; p < TAGS; p++) {
                float v = trow[p] + fv[p];
                if (v > best) { best = v; arg = p; }
            }
            bp[t][j] = (unsigned char)arg;
        }
        __syncwarp();
        if (j < TAGS) fv[j] = best + feat;
        __syncwarp();
    }

    if (j < TAGS) term[j] = fv[j] + transitions[STOP_TAG * TAGS + j];
    __syncwarp();
    if (j == 0) {
        float bs = term[0]; int bt = 0;
#pragma unroll
        for (int p = 1; p < TAGS; p++) if (term[p] > bs) { bs = term[p]; bt = p; }
        out[0] = bs;                       // path_score
        int cur = bt;
        out[SEQ] = (float)bt;              // path[4095]
        for (int t = SEQ - 1; t >= 1; --t) {
            cur = bp[t][cur];
            out[t] = (float)cur;           // path[t-1] -> out[1+(t-1)]
        }
    }
}

// ---------------- launcher ----------------------------------------------------
extern "C" void kernel_launch(void* const* d_in, const int* in_sizes, int n_in,
                              void* d_out, int out_size)
{
    const int*   sentence = (const int*)d_in[0];
    const float* emb      = (const float*)d_in[1];
    const float* w_ih_f   = (const float*)d_in[2];
    const float* w_hh_f   = (const float*)d_in[3];
    const float* b_ih_f   = (const float*)d_in[4];
    const float* b_hh_f   = (const float*)d_in[5];
    const float* w_ih_b   = (const float*)d_in[6];
    const float* w_hh_b   = (const float*)d_in[7];
    const float* b_ih_b   = (const float*)d_in[8];
    const float* b_hh_b   = (const float*)d_in[9];
    const float* w_tag    = (const float*)d_in[10];
    const float* b_tag    = (const float*)d_in[11];
    const float* trans    = (const float*)d_in[12];
    const float* h0       = (const float*)d_in[13];
    const float* c0       = (const float*)d_in[14];
    float* out = (float*)d_out;

    const int vit_smem = SEQ * TAGS + 128;   // 98432 bytes
    cudaFuncSetAttribute(viterbi_kernel,
                         cudaFuncAttributeMaxDynamicSharedMemorySize, vit_smem);

    init_kernel<<<1, 32>>>();

    dim3 ggrid(32, 32);
    gemm_xg_kernel<<<ggrid, 256>>>(sentence, emb, w_ih_f, w_ih_b,
                                   b_ih_f, b_hh_f, b_ih_b, b_hh_b);

    lstm_rec_kernel<<<128, 128>>>(w_hh_f, w_hh_b, h0, c0);

    feats_kernel<<<1024, 256>>>(w_tag, b_tag);

    viterbi_kernel<<<1, 32, vit_smem>>>(trans, out);
}